// round 15
// baseline (speedup 1.0000x reference)
#include <cuda_runtime.h>
#include <cuda_fp16.h>
#include <cstdint>

#define BATCH 4
#define SEQ 2048
#define DIM 1024
#define HEADS 16
#define DHEAD 64
#define INNER 1024
#define ROWS (BATCH * SEQ)      /* 8192 */
#define QKV_COLS (3 * INNER)    /* 3072 */
#define ATT_SCALE 0.125f

// ---------------- scratch (device globals) ----------------------------------
__device__ __half g_xf[(size_t)ROWS * DIM];
__device__ __half g_qkvf[(size_t)ROWS * QKV_COLS];
__device__ __half g_of[(size_t)ROWS * INNER];
__device__ __half g_wqkvf[(size_t)QKV_COLS * DIM];  // [N][K]
__device__ __half g_woutf[(size_t)DIM * INNER];     // [N][K]

// ---------------- work-queue / sync state (self-resetting) ------------------
#define WQT ((QKV_COLS / 32) * (DIM / 32))   /* 3072 w_qkv transpose tiles */
#define WOT ((DIM / 32) * (INNER / 32))      /* 1024 w_out transpose tiles */
#define XIT 512                              /* x-convert items (16 rows each) */
#define NP0 (WQT + WOT + XIT)                /* 4608 phase-0 items */
#define NQKV_TILES ((ROWS / 128) * (QKV_COLS / 128))   /* 1536 */
#define NATTN_TILES (16 * HEADS * BATCH)               /* 1024 */
#define NOUT_TILES ((ROWS / 128) * (DIM / 128))        /* 512  */
#define QKV_PER_BATCH ((ROWS / BATCH / 128) * (QKV_COLS / 128))  /* 384 */

__device__ int g_ctr[4];                 // phase claim counters
__device__ int g_wq, g_wo;               // weight-transpose done counts
__device__ int g_xd[ROWS / 128];         // x-convert done per rowblk (to 8)
__device__ int g_qkv_done[BATCH];
__device__ int g_attn_done[ROWS / 128];
__device__ int g_fin;

// ---------------------------------------------------------------------------
__device__ __forceinline__ uint32_t pack_h2(float a, float b) {
    __half2 h = __floats2half2_rn(a, b);
    return *(uint32_t*)&h;
}

// ---------------------------------------------------------------------------
#define LDSM4(r0, r1, r2, r3, addr)                                          \
    asm volatile("ldmatrix.sync.aligned.m8n8.x4.shared.b16 {%0,%1,%2,%3}, [%4];" \
                 : "=r"(r0), "=r"(r1), "=r"(r2), "=r"(r3) : "r"(addr))
#define LDSM4T(r0, r1, r2, r3, addr)                                         \
    asm volatile("ldmatrix.sync.aligned.m8n8.x4.trans.shared.b16 {%0,%1,%2,%3}, [%4];" \
                 : "=r"(r0), "=r"(r1), "=r"(r2), "=r"(r3) : "r"(addr))
#define MMAS(d, a0, a1, a2, a3, b0, b1)                                      \
    asm volatile("mma.sync.aligned.m16n8k16.row.col.f32.f16.f16.f32 "        \
                 "{%0,%1,%2,%3},{%4,%5,%6,%7},{%8,%9},{%0,%1,%2,%3};"        \
                 : "+f"(d[0]), "+f"(d[1]), "+f"(d[2]), "+f"(d[3])            \
                 : "r"(a0), "r"(a1), "r"(a2), "r"(a3), "r"(b0), "r"(b1))
#define MMAA(d, a, b)                                                        \
    MMAS(d, (a)[0], (a)[1], (a)[2], (a)[3], (b)[0], (b)[1])
#define CPASYNC16(dst, src)                                                  \
    asm volatile("cp.async.cg.shared.global [%0], [%1], 16;" :: "r"(dst), "l"(src))

// ---------------------------------------------------------------------------
// Phase-0 helpers (use dynamic smem as scratch)
// ---------------------------------------------------------------------------
__device__ void transpose_tile(const float* __restrict__ W,
                               __half* __restrict__ T,
                               int K, int N, int tileN, int tileK,
                               float* tbuf, int tid)
{
    // tbuf: 32x33 floats in dynamic smem
    int n0 = tileN * 32, k0 = tileK * 32;
    int tx = tid & 31, ty = tid >> 5;
#pragma unroll
    for (int j = 0; j < 4; j++)
        tbuf[(ty + j * 8) * 33 + tx] = W[(size_t)(k0 + ty + j * 8) * N + n0 + tx];
    __syncthreads();
#pragma unroll
    for (int j = 0; j < 4; j++) {
        float f = tbuf[tx * 33 + ty + j * 8];
        T[(size_t)(n0 + ty + j * 8) * K + k0 + tx] = __float2half_rn(f);
    }
    __syncthreads();   // tbuf reusable for next item
}

__device__ void xconv_item(const float* __restrict__ x,
                           __half* __restrict__ xf, int u, int tid)
{
    // item u covers 16 rows x 1024 cols: 2048 uint4 outputs
    size_t base_out = (size_t)u * 2048;
#pragma unroll
    for (int i = 0; i < 8; i++) {
        size_t o = base_out + tid + i * 256;
        float4 v0 = ((const float4*)x)[o * 2];
        float4 v1 = ((const float4*)x)[o * 2 + 1];
        uint4 w;
        w.x = pack_h2(v0.x, v0.y);
        w.y = pack_h2(v0.z, v0.w);
        w.z = pack_h2(v1.x, v1.y);
        w.w = pack_h2(v1.z, v1.w);
        ((uint4*)xf)[o] = w;
    }
}

// ---------------------------------------------------------------------------
// GEMM tile body (round-8 config, verbatim math).
// ---------------------------------------------------------------------------
#define GBK 64
#define GKP 72
#define GSTAGE (2 * 128 * GKP)
#define GNSTG 3
#define GSMEM (GNSTG * GSTAGE * 2)   /* 110592 bytes */

template <bool FP16_OUT>
__device__ void gemm_tile(
    const __half* __restrict__ A, const __half* __restrict__ B,
    const float* __restrict__ bias, float* __restrict__ C,
    __half* __restrict__ Ch, int N, int K, int brow, int bcol,
    uint32_t sbase, int tid)
{
    const int lane = tid & 31, warp = tid >> 5;
    const int wm = warp >> 1, wn = warp & 1;
    const int lrow = tid >> 3;
    const int lk = (tid & 7) << 3;

    float acc[2][8][4] = {};

    const int a_r = lane & 15;
    const int a_k = (lane >> 4) << 3;
    const int bg = lane >> 3;
    const int b_r = ((bg & 2) << 2) + (lane & 7);
    const int b_k = (bg & 1) << 3;
    const int NK = K / GBK;

    auto load_stage = [&](int st, int k0) {
        int base = st * GSTAGE;
#pragma unroll
        for (int i = 0; i < 4; i++) {
            int row = lrow + i * 32;
            uint32_t da = sbase + (uint32_t)(base + row * GKP + lk) * 2;
            CPASYNC16(da, A + (size_t)(brow + row) * K + k0 + lk);
            uint32_t db = sbase + (uint32_t)(base + 128 * GKP + row * GKP + lk) * 2;
            CPASYNC16(db, B + (size_t)(bcol + row) * K + k0 + lk);
        }
        asm volatile("cp.async.commit_group;");
    };

    load_stage(0, 0);
    load_stage(1, GBK);

    for (int kc = 0; kc < NK; kc++) {
        if (kc + 1 < NK) {
            asm volatile("cp.async.wait_group 1;");
        } else {
            asm volatile("cp.async.wait_group 0;");
        }
        __syncthreads();

        if (kc + 2 < NK)
            load_stage((kc + 2) % GNSTG, (kc + 2) * GBK);

        const int abase = (kc % GNSTG) * GSTAGE;
#pragma unroll
        for (int ks = 0; ks < 4; ks++) {
            uint32_t aH[2][4];
#pragma unroll
            for (int mt = 0; mt < 2; mt++) {
                uint32_t ad = sbase +
                    (uint32_t)(abase + (wm * 32 + mt * 16 + a_r) * GKP + ks * 16 + a_k) * 2;
                LDSM4(aH[mt][0], aH[mt][1], aH[mt][2], aH[mt][3], ad);
            }
#pragma unroll
            for (int half = 0; half < 2; half++) {
                uint32_t bH[4][2];
#pragma unroll
                for (int p = 0; p < 2; p++) {
                    uint32_t bd = sbase +
                        (uint32_t)(abase + 128 * GKP +
                                   (wn * 64 + half * 32 + p * 16 + b_r) * GKP +
                                   ks * 16 + b_k) * 2;
                    LDSM4(bH[2 * p][0], bH[2 * p][1], bH[2 * p + 1][0], bH[2 * p + 1][1], bd);
                }
#pragma unroll
                for (int mt = 0; mt < 2; mt++)
#pragma unroll
                    for (int j = 0; j < 4; j++)
                        MMAA(acc[mt][half * 4 + j], aH[mt], bH[j]);
            }
        }
    }
    __syncthreads();

#pragma unroll
    for (int mt = 0; mt < 2; mt++) {
        int row0 = brow + wm * 32 + mt * 16 + (lane >> 2);
#pragma unroll
        for (int nt = 0; nt < 8; nt++) {
            int col = bcol + wn * 64 + nt * 8 + ((lane & 3) << 1);
            float b0 = bias[col], b1 = bias[col + 1];
            float v00 = acc[mt][nt][0] + b0, v01 = acc[mt][nt][1] + b1;
            float v10 = acc[mt][nt][2] + b0, v11 = acc[mt][nt][3] + b1;
            if (FP16_OUT) {
                ((uint32_t*)Ch)[((size_t)row0 * N + col) >> 1] = pack_h2(v00, v01);
                ((uint32_t*)Ch)[((size_t)(row0 + 8) * N + col) >> 1] = pack_h2(v10, v11);
            } else {
                *(float2*)(C + (size_t)row0 * N + col) = make_float2(v00, v01);
                *(float2*)(C + (size_t)(row0 + 8) * N + col) = make_float2(v10, v11);
            }
        }
    }
}

// ---------------------------------------------------------------------------
// Attention tile body (round-11/13, verbatim math).
// ---------------------------------------------------------------------------
#define TQ 128
#define TK 64
#define PR 72
#define QELE (TQ * PR)
#define STG_ELE (2 * TK * PR)
#define ANSTG 3

__device__ void attn_tile(const __half* __restrict__ qkv,
                          __half* __restrict__ outf,
                          int qt, int h, int b, uint32_t sbase, int tid)
{
    const int lane = tid & 31, warp = tid >> 5;

    const int a_r = lane & 15;
    const int a_k = (lane >> 4) << 3;
    const int bg = lane >> 3;
    const int b_r = ((bg & 2) << 2) + (lane & 7);
    const int b_k = (bg & 1) << 3;
    const int tb_k = ((bg & 1) << 3) + (lane & 7);
    const int tb_n = (bg & 2) << 2;

    const size_t qrow0 = ((size_t)b * SEQ + (size_t)qt * TQ);

    auto load_kv = [&](int st, int t) {
        size_t krow0 = (size_t)b * SEQ + (size_t)t * TK;
#pragma unroll
        for (int m = 0; m < 2; m++) {
            int gofs = (m == 0 ? INNER : 2 * INNER) + h * DHEAD;
#pragma unroll
            for (int i = 0; i < 2; i++) {
                int c = i * 256 + tid;
                int row = c >> 3, col8 = (c & 7) << 3;
                uint32_t dst = sbase +
                    (uint32_t)(QELE + st * STG_ELE + m * TK * PR + row * PR + col8) * 2;
                CPASYNC16(dst, qkv + (krow0 + row) * QKV_COLS + gofs + col8);
            }
        }
        asm volatile("cp.async.commit_group;");
    };

    {
#pragma unroll
        for (int i = 0; i < 4; i++) {
            int c = i * 256 + tid;
            int row = c >> 3, col8 = (c & 7) << 3;
            uint32_t dst = sbase + (uint32_t)(row * PR + col8) * 2;
            CPASYNC16(dst, qkv + (qrow0 + row) * QKV_COLS + h * DHEAD + col8);
        }
    }
    load_kv(0, 0);
    load_kv(1, 1);

    uint32_t aQ[4][4];
    asm volatile("cp.async.wait_group 1;");
    __syncthreads();
    {
        const __half2 s2 = __floats2half2_rn(ATT_SCALE, ATT_SCALE);
#pragma unroll
        for (int ks = 0; ks < 4; ks++) {
            uint32_t ad = sbase + (uint32_t)((warp * 16 + a_r) * PR + ks * 16 + a_k) * 2;
            LDSM4(aQ[ks][0], aQ[ks][1], aQ[ks][2], aQ[ks][3], ad);
#pragma unroll
            for (int j = 0; j < 4; j++) {
                __half2 q = *(__half2*)&aQ[ks][j];
                q = __hmul2(q, s2);
                aQ[ks][j] = *(uint32_t*)&q;
            }
        }
    }

    float acc_o[8][4] = {};
    float mrow[2] = {-1e30f, -1e30f};
    float lrow[2] = {0.f, 0.f};

    const int NT = SEQ / TK;
    for (int t = 0; t < NT; t++) {
        if (t + 1 < NT) {
            asm volatile("cp.async.wait_group 1;");
        } else {
            asm volatile("cp.async.wait_group 0;");
        }
        __syncthreads();

        if (t + 2 < NT)
            load_kv((t + 2) % ANSTG, t + 2);

        const int kb = QELE + (t % ANSTG) * STG_ELE;

        float acc_s[8][4] = {};
#pragma unroll
        for (int ks = 0; ks < 4; ks++) {
            uint32_t bH[8][2];
#pragma unroll
            for (int p = 0; p < 4; p++) {
                uint32_t bd = sbase +
                    (uint32_t)(kb + (p * 16 + b_r) * PR + ks * 16 + b_k) * 2;
                LDSM4(bH[2 * p][0], bH[2 * p][1], bH[2 * p + 1][0], bH[2 * p + 1][1], bd);
            }
#pragma unroll
            for (int nt = 0; nt < 8; nt++)
                MMAA(acc_s[nt], aQ[ks], bH[nt]);
        }

        float corr[2];
#pragma unroll
        for (int r = 0; r < 2; r++) {
            float mx = -1e30f;
#pragma unroll
            for (int nt = 0; nt < 8; nt++)
                mx = fmaxf(mx, fmaxf(acc_s[nt][2 * r], acc_s[nt][2 * r + 1]));
            mx = fmaxf(mx, __shfl_xor_sync(0xffffffffu, mx, 1));
            mx = fmaxf(mx, __shfl_xor_sync(0xffffffffu, mx, 2));
            float mn = fmaxf(mrow[r], mx);
            corr[r] = __expf(mrow[r] - mn);
            mrow[r] = mn;
#pragma unroll
            for (int nt = 0; nt < 8; nt++) {
                acc_s[nt][2 * r] = __expf(acc_s[nt][2 * r] - mn);
                acc_s[nt][2 * r + 1] = __expf(acc_s[nt][2 * r + 1] - mn);
            }
#pragma unroll
            for (int nt = 0; nt < 8; nt++) {
                acc_o[nt][2 * r] *= corr[r];
                acc_o[nt][2 * r + 1] *= corr[r];
            }
        }

        const int vb = kb + TK * PR;
#pragma unroll
        for (int kc = 0; kc < 4; kc++) {
            uint32_t aP[4], vH[8][2];
#pragma unroll
            for (int j = 0; j < 4; j++) {
                int tile = 2 * kc + (j >> 1);
                int c0 = (j & 1) << 1;
                aP[j] = pack_h2(acc_s[tile][c0], acc_s[tile][c0 + 1]);
            }
#pragma unroll
            for (int p = 0; p < 4; p++) {
                uint32_t vd = sbase +
                    (uint32_t)(vb + (kc * 16 + tb_k) * PR + p * 16 + tb_n) * 2;
                LDSM4T(vH[2 * p][0], vH[2 * p][1], vH[2 * p + 1][0], vH[2 * p + 1][1], vd);
            }
#pragma unroll
            for (int nt = 0; nt < 8; nt++)
                MMAA(acc_o[nt], aP, vH[nt]);
        }

#pragma unroll
        for (int r = 0; r < 2; r++) {
            float sum = 0.f;
#pragma unroll
            for (int nt = 0; nt < 8; nt++)
                sum += acc_s[nt][2 * r] + acc_s[nt][2 * r + 1];
            sum += __shfl_xor_sync(0xffffffffu, sum, 1);
            sum += __shfl_xor_sync(0xffffffffu, sum, 2);
            lrow[r] = lrow[r] * corr[r] + sum;
        }
    }
    __syncthreads();

    float inv0 = 1.0f / lrow[0], inv1 = 1.0f / lrow[1];
    size_t row0 = qrow0 + warp * 16 + (lane >> 2);
#pragma unroll
    for (int nt = 0; nt < 8; nt++) {
        int col = h * DHEAD + nt * 8 + ((lane & 3) << 1);
        ((uint32_t*)outf)[(row0 * INNER + col) >> 1] =
            pack_h2(acc_o[nt][0] * inv0, acc_o[nt][1] * inv0);
        ((uint32_t*)outf)[((row0 + 8) * INNER + col) >> 1] =
            pack_h2(acc_o[nt][2] * inv1, acc_o[nt][3] * inv1);
    }
}

// ---------------------------------------------------------------------------
// Single persistent kernel: phase 0 convert -> 1 QKV -> 2 attn -> 3 out-proj.
// Counters self-reset at end of each run (last CTA via g_fin).
// ---------------------------------------------------------------------------
__global__ __launch_bounds__(256, 2) void mega(
    const float* __restrict__ x,
    const float* __restrict__ w_qkv, const float* __restrict__ w_out,
    const float* __restrict__ b_qkv, const float* __restrict__ b_out,
    float* __restrict__ out)
{
    extern __shared__ __half sm[];
    uint32_t sbase = (uint32_t)__cvta_generic_to_shared(sm);
    float* tbuf = (float*)sm;
    const int tid = threadIdx.x;
    __shared__ int s_slot;

    // ---- phase 0: conversions (weights first, then x by rowblk) ----
    for (;;) {
        if (tid == 0) s_slot = atomicAdd(&g_ctr[0], 1);
        __syncthreads();
        int t = s_slot;
        __syncthreads();
        if (t >= NP0) break;
        if (t < WQT) {
            transpose_tile(w_qkv, g_wqkvf, DIM, QKV_COLS,
                           t % (QKV_COLS / 32), t / (QKV_COLS / 32), tbuf, tid);
            if (tid == 0) { __threadfence(); atomicAdd(&g_wq, 1); }
        } else if (t < WQT + WOT) {
            int u = t - WQT;
            transpose_tile(w_out, g_woutf, INNER, DIM,
                           u % (DIM / 32), u / (DIM / 32), tbuf, tid);
            if (tid == 0) { __threadfence(); atomicAdd(&g_wo, 1); }
        } else {
            int u = t - WQT - WOT;          // 0..511, 16 rows each
            xconv_item(x, g_xf, u, tid);
            __syncthreads();
            if (tid == 0) { __threadfence(); atomicAdd(&g_xd[u >> 3], 1); }
        }
    }

    // ---- phase 1: QKV GEMM ----
    for (;;) {
        if (tid == 0) s_slot = atomicAdd(&g_ctr[1], 1);
        __syncthreads();
        int t = s_slot;
        __syncthreads();
        if (t >= NQKV_TILES) break;
        int rowblk = t / (QKV_COLS / 128);
        int colblk = t % (QKV_COLS / 128);
        if (tid == 0) {
            while (atomicAdd(&g_wq, 0) < WQT || atomicAdd(&g_xd[rowblk], 0) < 8)
                __nanosleep(200);
        }
        __syncthreads();
        __threadfence();
        gemm_tile<true>(g_xf, g_wqkvf, b_qkv, nullptr, g_qkvf,
                        QKV_COLS, DIM, rowblk * 128, colblk * 128, sbase, tid);
        __syncthreads();
        if (tid == 0) {
            __threadfence();
            atomicAdd(&g_qkv_done[rowblk / (ROWS / BATCH / 128)], 1);
        }
    }

    // ---- phase 2: attention ----
    for (;;) {
        if (tid == 0) s_slot = atomicAdd(&g_ctr[2], 1);
        __syncthreads();
        int t = s_slot;
        __syncthreads();
        if (t >= NATTN_TILES) break;
        int b = t / (16 * HEADS);
        int r = t % (16 * HEADS);
        int qt = r / HEADS, h = r % HEADS;
        if (tid == 0) {
            while (atomicAdd(&g_qkv_done[b], 0) < QKV_PER_BATCH) __nanosleep(200);
        }
        __syncthreads();
        __threadfence();
        attn_tile(g_qkvf, g_of, qt, h, b, sbase, tid);
        __syncthreads();
        if (tid == 0) {
            __threadfence();
            atomicAdd(&g_attn_done[b * 16 + qt], 1);
        }
    }

    // ---- phase 3: out-proj GEMM ----
    for (;;) {
        if (tid == 0) s_slot = atomicAdd(&g_ctr[3], 1);
        __syncthreads();
        int t = s_slot;
        __syncthreads();
        if (t >= NOUT_TILES) break;
        int rowblk = t / (DIM / 128);
        int colblk = t % (DIM / 128);
        if (tid == 0) {
            while (atomicAdd(&g_attn_done[rowblk], 0) < HEADS ||
                   atomicAdd(&g_wo, 0) < WOT)
                __nanosleep(200);
        }
        __syncthreads();
        __threadfence();
        gemm_tile<false>(g_of, g_woutf, b_out, out, nullptr,
                         DIM, INNER, rowblk * 128, colblk * 128, sbase, tid);
        __syncthreads();
    }

    // ---- end-of-run reset (last CTA zeroes all state for next replay) ----
    __threadfence();
    __syncthreads();
    if (tid == 0) {
        int old = atomicAdd(&g_fin, 1);
        if (old == (int)gridDim.x - 1) {
            g_ctr[0] = 0; g_ctr[1] = 0; g_ctr[2] = 0; g_ctr[3] = 0;
            g_wq = 0; g_wo = 0;
#pragma unroll
            for (int i = 0; i < ROWS / 128; i++) { g_xd[i] = 0; g_attn_done[i] = 0; }
#pragma unroll
            for (int i = 0; i < BATCH; i++) g_qkv_done[i] = 0;
            g_fin = 0;
            __threadfence();
        }
    }
}

// ---------------------------------------------------------------------------
extern "C" void kernel_launch(void* const* d_in, const int* in_sizes, int n_in,
                              void* d_out, int out_size)
{
    const float* x     = (const float*)d_in[0];
    const float* w_qkv = (const float*)d_in[1];
    const float* b_qkv = (const float*)d_in[2];
    const float* w_out = (const float*)d_in[3];
    const float* b_out = (const float*)d_in[4];
    float* out = (float*)d_out;

    int nsm = 148;
    cudaDeviceGetAttribute(&nsm, cudaDevAttrMultiProcessorCount, 0);

    cudaFuncSetAttribute(mega, cudaFuncAttributeMaxDynamicSharedMemorySize, GSMEM);

    mega<<<nsm * 2, 256, GSMEM>>>(x, w_qkv, w_out, b_qkv, b_out, out);
}

// round 16
// speedup vs baseline: 1.0526x; 1.0526x over previous
#include <cuda_runtime.h>
#include <cuda_fp16.h>
#include <cstdint>

#define BATCH 4
#define SEQ 2048
#define DIM 1024
#define HEADS 16
#define DHEAD 64
#define INNER 1024
#define ROWS (BATCH * SEQ)      /* 8192 */
#define QKV_COLS (3 * INNER)    /* 3072 */
#define ATT_SCALE 0.125f

// ---------------- scratch (device globals) ----------------------------------
__device__ __half g_xf[(size_t)ROWS * DIM];
__device__ __half g_qkvf[(size_t)ROWS * QKV_COLS];
__device__ __half g_of[(size_t)ROWS * INNER];
__device__ __half g_wqkvf[(size_t)QKV_COLS * DIM];  // [N][K]
__device__ __half g_woutf[(size_t)DIM * INNER];     // [N][K]

// ---------------- cross-phase sync state (zeroed in fused_convert) ----------
#define NQKV_TILES ((ROWS / 128) * (QKV_COLS / 128))   /* 1536 */
#define NATTN_TILES (16 * HEADS * BATCH)               /* 1024 */
#define NOUT_TILES ((ROWS / 128) * (DIM / 128))        /* 512  */
#define QKV_PER_BATCH ((ROWS / BATCH / 128) * (QKV_COLS / 128))  /* 384 */

__device__ int g_ctr[3];
__device__ int g_qkv_done[BATCH];
__device__ int g_attn_done[ROWS / 128];   /* 64 */

// ---------------------------------------------------------------------------
__device__ __forceinline__ uint32_t pack_h2(float a, float b) {
    __half2 h = __floats2half2_rn(a, b);
    return *(uint32_t*)&h;
}

// ---------------------------------------------------------------------------
// Fused conversion kernel + sync-state reset (round-13 form: 8192-block
// parallelism, DRAM-bound floor).
// ---------------------------------------------------------------------------
#define XB (ROWS * DIM / 8 / 256)          /* 4096 blocks */
#define QB ((QKV_COLS / 32) * (DIM / 32))  /* 3072 blocks */
#define OB ((DIM / 32) * (INNER / 32))     /* 1024 blocks */

__device__ __forceinline__ void transpose_tile(
    const float* __restrict__ W, __half* __restrict__ T,
    int K, int N, int tileN, int tileK, int tid)
{
    __shared__ float t[32][33];
    int n0 = tileN * 32, k0 = tileK * 32;
    int tx = tid & 31, ty = tid >> 5;
#pragma unroll
    for (int j = 0; j < 4; j++)
        t[ty + j * 8][tx] = W[(size_t)(k0 + ty + j * 8) * N + n0 + tx];
    __syncthreads();
#pragma unroll
    for (int j = 0; j < 4; j++) {
        float f = t[tx][ty + j * 8];
        T[(size_t)(n0 + ty + j * 8) * K + k0 + tx] = __float2half_rn(f);
    }
}

__global__ void fused_convert(const float* __restrict__ x,
                              const float* __restrict__ w_qkv,
                              const float* __restrict__ w_out,
                              __half* __restrict__ xf,
                              __half* __restrict__ wqf,
                              __half* __restrict__ wof)
{
    const int bid = blockIdx.x;
    const int tid = threadIdx.x;
    if (bid == 0) {
        if (tid < 3) g_ctr[tid] = 0;
        if (tid >= 3 && tid < 3 + BATCH) g_qkv_done[tid - 3] = 0;
        if (tid >= 8 && tid < 8 + ROWS / 128) g_attn_done[tid - 8] = 0;
    }
    if (bid < XB) {
        size_t i = ((size_t)bid * 256 + tid) * 2;
        float4 v0 = ((const float4*)x)[i];
        float4 v1 = ((const float4*)x)[i + 1];
        uint4 o;
        o.x = pack_h2(v0.x, v0.y);
        o.y = pack_h2(v0.z, v0.w);
        o.z = pack_h2(v1.x, v1.y);
        o.w = pack_h2(v1.z, v1.w);
        ((uint4*)xf)[(size_t)bid * 256 + tid] = o;
    } else if (bid < XB + QB) {
        int t = bid - XB;
        transpose_tile(w_qkv, wqf, DIM, QKV_COLS, t % (QKV_COLS / 32),
                       t / (QKV_COLS / 32), tid);
    } else {
        int t = bid - XB - QB;
        transpose_tile(w_out, wof, INNER, DIM, t % (DIM / 32),
                       t / (DIM / 32), tid);
    }
}

// ---------------------------------------------------------------------------
#define LDSM4(r0, r1, r2, r3, addr)                                          \
    asm volatile("ldmatrix.sync.aligned.m8n8.x4.shared.b16 {%0,%1,%2,%3}, [%4];" \
                 : "=r"(r0), "=r"(r1), "=r"(r2), "=r"(r3) : "r"(addr))
#define LDSM4T(r0, r1, r2, r3, addr)                                         \
    asm volatile("ldmatrix.sync.aligned.m8n8.x4.trans.shared.b16 {%0,%1,%2,%3}, [%4];" \
                 : "=r"(r0), "=r"(r1), "=r"(r2), "=r"(r3) : "r"(addr))
#define MMAS(d, a0, a1, a2, a3, b0, b1)                                      \
    asm volatile("mma.sync.aligned.m16n8k16.row.col.f32.f16.f16.f32 "        \
                 "{%0,%1,%2,%3},{%4,%5,%6,%7},{%8,%9},{%0,%1,%2,%3};"        \
                 : "+f"(d[0]), "+f"(d[1]), "+f"(d[2]), "+f"(d[3])            \
                 : "r"(a0), "r"(a1), "r"(a2), "r"(a3), "r"(b0), "r"(b1))
#define MMAA(d, a, b)                                                        \
    MMAS(d, (a)[0], (a)[1], (a)[2], (a)[3], (b)[0], (b)[1])
#define CPASYNC16(dst, src)                                                  \
    asm volatile("cp.async.cg.shared.global [%0], [%1], 16;" :: "r"(dst), "l"(src))

// ---------------------------------------------------------------------------
// GEMM tile body (round-8 config, verbatim math).
// ---------------------------------------------------------------------------
#define GBK 64
#define GKP 72
#define GSTAGE (2 * 128 * GKP)
#define GNSTG 3
#define GSMEM (GNSTG * GSTAGE * 2)   /* 110592 bytes */

template <bool FP16_OUT>
__device__ void gemm_tile(
    const __half* __restrict__ A, const __half* __restrict__ B,
    const float* __restrict__ bias, float* __restrict__ C,
    __half* __restrict__ Ch, int N, int K, int brow, int bcol,
    uint32_t sbase, int tid)
{
    const int lane = tid & 31, warp = tid >> 5;
    const int wm = warp >> 1, wn = warp & 1;
    const int lrow = tid >> 3;
    const int lk = (tid & 7) << 3;

    float acc[2][8][4] = {};

    const int a_r = lane & 15;
    const int a_k = (lane >> 4) << 3;
    const int bg = lane >> 3;
    const int b_r = ((bg & 2) << 2) + (lane & 7);
    const int b_k = (bg & 1) << 3;
    const int NK = K / GBK;

    auto load_stage = [&](int st, int k0) {
        int base = st * GSTAGE;
#pragma unroll
        for (int i = 0; i < 4; i++) {
            int row = lrow + i * 32;
            uint32_t da = sbase + (uint32_t)(base + row * GKP + lk) * 2;
            CPASYNC16(da, A + (size_t)(brow + row) * K + k0 + lk);
            uint32_t db = sbase + (uint32_t)(base + 128 * GKP + row * GKP + lk) * 2;
            CPASYNC16(db, B + (size_t)(bcol + row) * K + k0 + lk);
        }
        asm volatile("cp.async.commit_group;");
    };

    load_stage(0, 0);
    load_stage(1, GBK);

    for (int kc = 0; kc < NK; kc++) {
        if (kc + 1 < NK) {
            asm volatile("cp.async.wait_group 1;");
        } else {
            asm volatile("cp.async.wait_group 0;");
        }
        __syncthreads();

        if (kc + 2 < NK)
            load_stage((kc + 2) % GNSTG, (kc + 2) * GBK);

        const int abase = (kc % GNSTG) * GSTAGE;
#pragma unroll
        for (int ks = 0; ks < 4; ks++) {
            uint32_t aH[2][4];
#pragma unroll
            for (int mt = 0; mt < 2; mt++) {
                uint32_t ad = sbase +
                    (uint32_t)(abase + (wm * 32 + mt * 16 + a_r) * GKP + ks * 16 + a_k) * 2;
                LDSM4(aH[mt][0], aH[mt][1], aH[mt][2], aH[mt][3], ad);
            }
#pragma unroll
            for (int half = 0; half < 2; half++) {
                uint32_t bH[4][2];
#pragma unroll
                for (int p = 0; p < 2; p++) {
                    uint32_t bd = sbase +
                        (uint32_t)(abase + 128 * GKP +
                                   (wn * 64 + half * 32 + p * 16 + b_r) * GKP +
                                   ks * 16 + b_k) * 2;
                    LDSM4(bH[2 * p][0], bH[2 * p][1], bH[2 * p + 1][0], bH[2 * p + 1][1], bd);
                }
#pragma unroll
                for (int mt = 0; mt < 2; mt++)
#pragma unroll
                    for (int j = 0; j < 4; j++)
                        MMAA(acc[mt][half * 4 + j], aH[mt], bH[j]);
            }
        }
    }
    __syncthreads();

#pragma unroll
    for (int mt = 0; mt < 2; mt++) {
        int row0 = brow + wm * 32 + mt * 16 + (lane >> 2);
#pragma unroll
        for (int nt = 0; nt < 8; nt++) {
            int col = bcol + wn * 64 + nt * 8 + ((lane & 3) << 1);
            float b0 = bias[col], b1 = bias[col + 1];
            float v00 = acc[mt][nt][0] + b0, v01 = acc[mt][nt][1] + b1;
            float v10 = acc[mt][nt][2] + b0, v11 = acc[mt][nt][3] + b1;
            if (FP16_OUT) {
                ((uint32_t*)Ch)[((size_t)row0 * N + col) >> 1] = pack_h2(v00, v01);
                ((uint32_t*)Ch)[((size_t)(row0 + 8) * N + col) >> 1] = pack_h2(v10, v11);
            } else {
                *(float2*)(C + (size_t)row0 * N + col) = make_float2(v00, v01);
                *(float2*)(C + (size_t)(row0 + 8) * N + col) = make_float2(v10, v11);
            }
        }
    }
}

// ---------------------------------------------------------------------------
// Attention tile body (round-11/13, verbatim math).
// ---------------------------------------------------------------------------
#define TQ 128
#define TK 64
#define PR 72
#define QELE (TQ * PR)
#define STG_ELE (2 * TK * PR)
#define ANSTG 3

__device__ void attn_tile(const __half* __restrict__ qkv,
                          __half* __restrict__ outf,
                          int qt, int h, int b, uint32_t sbase, int tid)
{
    const int lane = tid & 31, warp = tid >> 5;

    const int a_r = lane & 15;
    const int a_k = (lane >> 4) << 3;
    const int bg = lane >> 3;
    const int b_r = ((bg & 2) << 2) + (lane & 7);
    const int b_k = (bg & 1) << 3;
    const int tb_k = ((bg & 1) << 3) + (lane & 7);
    const int tb_n = (bg & 2) << 2;

    const size_t qrow0 = ((size_t)b * SEQ + (size_t)qt * TQ);

    auto load_kv = [&](int st, int t) {
        size_t krow0 = (size_t)b * SEQ + (size_t)t * TK;
#pragma unroll
        for (int m = 0; m < 2; m++) {
            int gofs = (m == 0 ? INNER : 2 * INNER) + h * DHEAD;
#pragma unroll
            for (int i = 0; i < 2; i++) {
                int c = i * 256 + tid;
                int row = c >> 3, col8 = (c & 7) << 3;
                uint32_t dst = sbase +
                    (uint32_t)(QELE + st * STG_ELE + m * TK * PR + row * PR + col8) * 2;
                CPASYNC16(dst, qkv + (krow0 + row) * QKV_COLS + gofs + col8);
            }
        }
        asm volatile("cp.async.commit_group;");
    };

    {
#pragma unroll
        for (int i = 0; i < 4; i++) {
            int c = i * 256 + tid;
            int row = c >> 3, col8 = (c & 7) << 3;
            uint32_t dst = sbase + (uint32_t)(row * PR + col8) * 2;
            CPASYNC16(dst, qkv + (qrow0 + row) * QKV_COLS + h * DHEAD + col8);
        }
    }
    load_kv(0, 0);
    load_kv(1, 1);

    uint32_t aQ[4][4];
    asm volatile("cp.async.wait_group 1;");
    __syncthreads();
    {
        const __half2 s2 = __floats2half2_rn(ATT_SCALE, ATT_SCALE);
#pragma unroll
        for (int ks = 0; ks < 4; ks++) {
            uint32_t ad = sbase + (uint32_t)((warp * 16 + a_r) * PR + ks * 16 + a_k) * 2;
            LDSM4(aQ[ks][0], aQ[ks][1], aQ[ks][2], aQ[ks][3], ad);
#pragma unroll
            for (int j = 0; j < 4; j++) {
                __half2 q = *(__half2*)&aQ[ks][j];
                q = __hmul2(q, s2);
                aQ[ks][j] = *(uint32_t*)&q;
            }
        }
    }

    float acc_o[8][4] = {};
    float mrow[2] = {-1e30f, -1e30f};
    float lrow[2] = {0.f, 0.f};

    const int NT = SEQ / TK;
    for (int t = 0; t < NT; t++) {
        if (t + 1 < NT) {
            asm volatile("cp.async.wait_group 1;");
        } else {
            asm volatile("cp.async.wait_group 0;");
        }
        __syncthreads();

        if (t + 2 < NT)
            load_kv((t + 2) % ANSTG, t + 2);

        const int kb = QELE + (t % ANSTG) * STG_ELE;

        float acc_s[8][4] = {};
#pragma unroll
        for (int ks = 0; ks < 4; ks++) {
            uint32_t bH[8][2];
#pragma unroll
            for (int p = 0; p < 4; p++) {
                uint32_t bd = sbase +
                    (uint32_t)(kb + (p * 16 + b_r) * PR + ks * 16 + b_k) * 2;
                LDSM4(bH[2 * p][0], bH[2 * p][1], bH[2 * p + 1][0], bH[2 * p + 1][1], bd);
            }
#pragma unroll
            for (int nt = 0; nt < 8; nt++)
                MMAA(acc_s[nt], aQ[ks], bH[nt]);
        }

        float corr[2];
#pragma unroll
        for (int r = 0; r < 2; r++) {
            float mx = -1e30f;
#pragma unroll
            for (int nt = 0; nt < 8; nt++)
                mx = fmaxf(mx, fmaxf(acc_s[nt][2 * r], acc_s[nt][2 * r + 1]));
            mx = fmaxf(mx, __shfl_xor_sync(0xffffffffu, mx, 1));
            mx = fmaxf(mx, __shfl_xor_sync(0xffffffffu, mx, 2));
            float mn = fmaxf(mrow[r], mx);
            corr[r] = __expf(mrow[r] - mn);
            mrow[r] = mn;
#pragma unroll
            for (int nt = 0; nt < 8; nt++) {
                acc_s[nt][2 * r] = __expf(acc_s[nt][2 * r] - mn);
                acc_s[nt][2 * r + 1] = __expf(acc_s[nt][2 * r + 1] - mn);
            }
#pragma unroll
            for (int nt = 0; nt < 8; nt++) {
                acc_o[nt][2 * r] *= corr[r];
                acc_o[nt][2 * r + 1] *= corr[r];
            }
        }

        const int vb = kb + TK * PR;
#pragma unroll
        for (int kc = 0; kc < 4; kc++) {
            uint32_t aP[4], vH[8][2];
#pragma unroll
            for (int j = 0; j < 4; j++) {
                int tile = 2 * kc + (j >> 1);
                int c0 = (j & 1) << 1;
                aP[j] = pack_h2(acc_s[tile][c0], acc_s[tile][c0 + 1]);
            }
#pragma unroll
            for (int p = 0; p < 4; p++) {
                uint32_t vd = sbase +
                    (uint32_t)(vb + (kc * 16 + tb_k) * PR + p * 16 + tb_n) * 2;
                LDSM4T(vH[2 * p][0], vH[2 * p][1], vH[2 * p + 1][0], vH[2 * p + 1][1], vd);
            }
#pragma unroll
            for (int nt = 0; nt < 8; nt++)
                MMAA(acc_o[nt], aP, vH[nt]);
        }

#pragma unroll
        for (int r = 0; r < 2; r++) {
            float sum = 0.f;
#pragma unroll
            for (int nt = 0; nt < 8; nt++)
                sum += acc_s[nt][2 * r] + acc_s[nt][2 * r + 1];
            sum += __shfl_xor_sync(0xffffffffu, sum, 1);
            sum += __shfl_xor_sync(0xffffffffu, sum, 2);
            lrow[r] = lrow[r] * corr[r] + sum;
        }
    }
    __syncthreads();

    float inv0 = 1.0f / lrow[0], inv1 = 1.0f / lrow[1];
    size_t row0 = qrow0 + warp * 16 + (lane >> 2);
#pragma unroll
    for (int nt = 0; nt < 8; nt++) {
        int col = h * DHEAD + nt * 8 + ((lane & 3) << 1);
        ((uint32_t*)outf)[(row0 * INNER + col) >> 1] =
            pack_h2(acc_o[nt][0] * inv0, acc_o[nt][1] * inv0);
        ((uint32_t*)outf)[((row0 + 8) * INNER + col) >> 1] =
            pack_h2(acc_o[nt][2] * inv1, acc_o[nt][3] * inv1);
    }
}

// ---------------------------------------------------------------------------
// Persistent fused kernel (round-14 structure + double-buffered claim
// broadcast + volatile spins).
// ---------------------------------------------------------------------------
__global__ __launch_bounds__(256, 2) void mega(
    const float* __restrict__ b_qkv, const float* __restrict__ b_out,
    float* __restrict__ out)
{
    extern __shared__ __half sm[];
    uint32_t sbase = (uint32_t)__cvta_generic_to_shared(sm);
    const int tid = threadIdx.x;
    __shared__ int s_slot[2];

    volatile int* vqkv = (volatile int*)g_qkv_done;
    volatile int* vattn = (volatile int*)g_attn_done;

    // ---- phase 1: QKV GEMM ----
    for (int it = 0;; it++) {
        const int pb = it & 1;
        if (tid == 0) s_slot[pb] = atomicAdd(&g_ctr[0], 1);
        __syncthreads();
        int t = s_slot[pb];
        if (t >= NQKV_TILES) break;
        int rowblk = t / (QKV_COLS / 128);
        int colblk = t % (QKV_COLS / 128);
        gemm_tile<true>(g_xf, g_wqkvf, b_qkv, nullptr, g_qkvf,
                        QKV_COLS, DIM, rowblk * 128, colblk * 128, sbase, tid);
        __syncthreads();
        if (tid == 0) {
            __threadfence();
            atomicAdd(&g_qkv_done[rowblk / (ROWS / BATCH / 128)], 1);
        }
    }

    // ---- phase 2: attention ----
    for (int it = 0;; it++) {
        const int pb = it & 1;
        if (tid == 0) s_slot[pb] = atomicAdd(&g_ctr[1], 1);
        __syncthreads();
        int t = s_slot[pb];
        if (t >= NATTN_TILES) break;
        int b = t / (16 * HEADS);
        int r = t % (16 * HEADS);
        int qt = r / HEADS, h = r % HEADS;
        if (tid == 0) {
            while (vqkv[b] < QKV_PER_BATCH) __nanosleep(200);
        }
        __syncthreads();
        __threadfence();
        attn_tile(g_qkvf, g_of, qt, h, b, sbase, tid);
        __syncthreads();
        if (tid == 0) {
            __threadfence();
            atomicAdd(&g_attn_done[b * 16 + qt], 1);
        }
    }

    // ---- phase 3: out-proj GEMM ----
    for (int it = 0;; it++) {
        const int pb = it & 1;
        if (tid == 0) s_slot[pb] = atomicAdd(&g_ctr[2], 1);
        __syncthreads();
        int t = s_slot[pb];
        if (t >= NOUT_TILES) break;
        int rowblk = t / (DIM / 128);
        int colblk = t % (DIM / 128);
        if (tid == 0) {
            while (vattn[rowblk] < HEADS) __nanosleep(200);
        }
        __syncthreads();
        __threadfence();
        gemm_tile<false>(g_of, g_woutf, b_out, out, nullptr,
                         DIM, INNER, rowblk * 128, colblk * 128, sbase, tid);
        __syncthreads();
    }
}

// ---------------------------------------------------------------------------
extern "C" void kernel_launch(void* const* d_in, const int* in_sizes, int n_in,
                              void* d_out, int out_size)
{
    const float* x     = (const float*)d_in[0];
    const float* w_qkv = (const float*)d_in[1];
    const float* b_qkv = (const float*)d_in[2];
    const float* w_out = (const float*)d_in[3];
    const float* b_out = (const float*)d_in[4];
    float* out = (float*)d_out;

    __half *xf, *wqf, *wof;
    cudaGetSymbolAddress((void**)&xf, g_xf);
    cudaGetSymbolAddress((void**)&wqf, g_wqkvf);
    cudaGetSymbolAddress((void**)&wof, g_woutf);

    int nsm = 148;
    cudaDeviceGetAttribute(&nsm, cudaDevAttrMultiProcessorCount, 0);

    cudaFuncSetAttribute(mega, cudaFuncAttributeMaxDynamicSharedMemorySize, GSMEM);

    // 0) fused conversions + sync-state reset (8192-block parallelism)
    fused_convert<<<XB + QB + OB, 256>>>(x, w_qkv, w_out, xf, wqf, wof);

    // 1) persistent fused QKV -> attention -> out-proj
    mega<<<nsm * 2, 256, GSMEM>>>(b_qkv, b_out, out);
}